// round 16
// baseline (speedup 1.0000x reference)
#include <cuda_runtime.h>
#include <cuda.h>
#include <cuda_fp16.h>
#include <cstdint>

// ---------------------------------------------------------------------------
// Problem dims (fixed for this problem instance)
// ---------------------------------------------------------------------------
static constexpr int MDIM = 8192;    // 4*2048 rows of X
static constexpr int NDIM = 16384;   // output features
static constexpr int KDIM = 4096;    // inner dim

// GEMM tiling (base-sm_103 path: TMA + ldmatrix + mma.sync.m16n8k16)
// R14 config (best known, 2382us): KC=64, 4-deep ring, persistent CTAs.
static constexpr int TM = 128;                // CTA M tile
static constexpr int TN = 256;                // CTA N tile
static constexpr int KC = 64;                 // K elems (f16) per stage = 128B rows
static constexpr int NSTAGES = 4;
static constexpr int KITERS = KDIM / KC;      // 64
static constexpr int TILES_M = MDIM / TM;     // 64
static constexpr int TILES_N = NDIM / TN;     // 64
static constexpr int NTILES = TILES_M * TILES_N;  // 4096
static constexpr int GROUP_M = 64;            // full column: X read from DRAM once

static constexpr int STAGE_A = TM * KC * 2;   // 16384 B
static constexpr int STAGE_B = TN * KC * 2;   // 32768 B
static constexpr uint32_t STAGE_BYTES = STAGE_A + STAGE_B;  // 49152

// Dynamic SMEM layout
static constexpr int OFF_FULL  = 0;
static constexpr int OFF_EMPTY = OFF_FULL + NSTAGES * 8;
static constexpr int OFF_A     = 1024;
static constexpr int OFF_B     = OFF_A + NSTAGES * STAGE_A;   // 66560
static constexpr int SMEM_TOTAL = OFF_B + NSTAGES * STAGE_B;  // 197632

static constexpr int NTHREADS = 544;  // 16 compute warps + 1 TMA warp
static constexpr int GRID = 152;      // persistent: one CTA per GB300 SM

// fp16 scratch (static device arrays: the sanctioned scratch mechanism)
__device__ __half g_X[(size_t)MDIM * KDIM];   // 64 MB
__device__ __half g_W[(size_t)NDIM * KDIM];   // 128 MB

// ---------------------------------------------------------------------------
// PTX helpers (base sm_103-safe: no tcgen05 anywhere)
// ---------------------------------------------------------------------------
__device__ __forceinline__ uint32_t smem_u32(const void* p) {
    uint32_t a;
    asm("{ .reg .u64 t; cvta.to.shared.u64 t, %1; cvt.u32.u64 %0, t; }"
        : "=r"(a) : "l"(p));
    return a;
}
__device__ __forceinline__ void mbar_init(uint32_t addr, uint32_t count) {
    asm volatile("mbarrier.init.shared.b64 [%0], %1;" :: "r"(addr), "r"(count) : "memory");
}
__device__ __forceinline__ void mbar_expect_tx(uint32_t addr, uint32_t bytes) {
    asm volatile("mbarrier.arrive.expect_tx.shared.b64 _, [%0], %1;"
                 :: "r"(addr), "r"(bytes) : "memory");
}
__device__ __forceinline__ void mbar_arrive(uint32_t addr) {
    asm volatile("mbarrier.arrive.shared.b64 _, [%0];" :: "r"(addr) : "memory");
}
__device__ __forceinline__ void mbar_wait(uint32_t addr, uint32_t phase) {
    asm volatile(
        "{\n\t"
        ".reg .pred P1;\n\t"
        "LAB_WAIT_%=:\n\t"
        "mbarrier.try_wait.parity.acquire.cta.shared::cta.b64 P1, [%0], %1, 0x989680;\n\t"
        "@P1 bra.uni DONE_%=;\n\t"
        "bra.uni LAB_WAIT_%=;\n\t"
        "DONE_%=:\n\t"
        "}"
        :: "r"(addr), "r"(phase) : "memory");
}
__device__ __forceinline__ void tma_load_2d(uint32_t smem_addr, const CUtensorMap* tmap,
                                            int cx, int cy, uint32_t mbar) {
    asm volatile(
        "cp.async.bulk.tensor.2d.shared::cta.global.tile.mbarrier::complete_tx::bytes "
        "[%0], [%1, {%2, %3}], [%4];"
        :: "r"(smem_addr), "l"(tmap), "r"(cx), "r"(cy), "r"(mbar) : "memory");
}
__device__ __forceinline__ void ldsm_x4(uint32_t* r, uint32_t addr) {
    asm volatile("ldmatrix.sync.aligned.m8n8.x4.shared.b16 {%0,%1,%2,%3}, [%4];"
                 : "=r"(r[0]), "=r"(r[1]), "=r"(r[2]), "=r"(r[3]) : "r"(addr));
}
__device__ __forceinline__ void mma16816(float* c, const uint32_t* a,
                                         uint32_t b0, uint32_t b1) {
    asm volatile(
        "mma.sync.aligned.m16n8k16.row.col.f32.f16.f16.f32 "
        "{%0,%1,%2,%3}, {%4,%5,%6,%7}, {%8,%9}, {%0,%1,%2,%3};"
        : "+f"(c[0]), "+f"(c[1]), "+f"(c[2]), "+f"(c[3])
        : "r"(a[0]), "r"(a[1]), "r"(a[2]), "r"(a[3]), "r"(b0), "r"(b1));
}

// Tile index -> (m_tile, n_tile). GROUP_M=64 => single group: m fastest, so
// the 152 in-flight CTAs span all 64 m-tiles at ~2.4 consecutive n-columns;
// the full 64MB A panel set stays L2-resident and X is read from DRAM once.
__device__ __forceinline__ void map_tile(int t, int& m_tile, int& n_tile) {
    m_tile = t % TILES_M;
    n_tile = t / TILES_M;
}

// ---------------------------------------------------------------------------
// Kernel 1: f32 -> f16 conversion for BOTH arrays in one launch
// (float4 in, 4x block-strided for MLP; single launch removes the
//  inter-kernel bubble and overlaps X-tail with W-head across SMs)
// ---------------------------------------------------------------------------
__global__ void fp8lin_convert2_kernel(const float4* __restrict__ inX,
                                       uint2* __restrict__ outX, int nX4,
                                       const float4* __restrict__ inW,
                                       uint2* __restrict__ outW, int nW4) {
    int base = blockIdx.x * (blockDim.x * 4) + threadIdx.x;
#pragma unroll
    for (int u = 0; u < 4; ++u) {
        int idx = base + u * blockDim.x;
        const float4* in;
        uint2* out;
        int rel;
        if (idx < nX4) {
            in = inX; out = outX; rel = idx;
        } else if (idx < nX4 + nW4) {
            in = inW; out = outW; rel = idx - nX4;
        } else {
            continue;
        }
        float4 v = in[rel];
        __half2 a = __floats2half2_rn(v.x, v.y);
        __half2 b = __floats2half2_rn(v.z, v.w);
        uint2 o;
        o.x = *reinterpret_cast<uint32_t*>(&a);
        o.y = *reinterpret_cast<uint32_t*>(&b);
        out[rel] = o;
    }
}

// ---------------------------------------------------------------------------
// Kernel 2: PERSISTENT pipelined HMMA GEMM  Y = Xf16 @ Wf16^T + bias
// 544 threads: warps 0-15 compute (4x4 warp grid, 32x64 tile each),
//              warp 16 = TMA producer.
// Each CTA loops over ~27 tiles; the stage ring runs CONTINUOUSLY across
// tile boundaries, so the producer prefetches tile t+1 during tile t's
// epilogue and the MMA pipe restarts instantly after the stores.
// ---------------------------------------------------------------------------
__global__ void __launch_bounds__(NTHREADS, 1)
fp8lin_gemm_kernel(const __grid_constant__ CUtensorMap tmA,
                   const __grid_constant__ CUtensorMap tmB,
                   const float* __restrict__ bias,
                   float* __restrict__ out) {
    extern __shared__ char smem[];
    const uint32_t sbase = smem_u32(smem);
    const int tid = threadIdx.x;
    const int wid = tid >> 5;
    const int lane = tid & 31;

    const uint32_t full0 = sbase + OFF_FULL;
    const uint32_t empty0 = sbase + OFF_EMPTY;

    if (tid == 0) {
        for (int s = 0; s < NSTAGES; ++s) {
            mbar_init(full0 + 8 * s, 1);    // completed by TMA tx bytes
            mbar_init(empty0 + 8 * s, 16);  // released by 16 compute warps
        }
    }
    __syncthreads();

    if (wid == 16) {
        // ---- TMA producer: stream all tiles' K-stages through one ring ----
        if (lane == 0) {
            int s = 0;
            uint32_t phase = 1;  // fresh barrier: parity-1 wait passes immediately
            for (int t = blockIdx.x; t < NTILES; t += GRID) {
                int m_tile, n_tile;
                map_tile(t, m_tile, n_tile);
                const int my = m_tile * TM, ny = n_tile * TN;
                for (int it = 0; it < KITERS; ++it) {
                    mbar_wait(empty0 + 8 * s, phase);
                    mbar_expect_tx(full0 + 8 * s, STAGE_BYTES);
                    tma_load_2d(sbase + OFF_A + s * STAGE_A, &tmA, it * KC, my,
                                full0 + 8 * s);
                    tma_load_2d(sbase + OFF_B + s * STAGE_B, &tmB, it * KC, ny,
                                full0 + 8 * s);
                    if (++s == NSTAGES) { s = 0; phase ^= 1; }
                }
            }
        }
        return;
    }

    // ---- compute warps: 4x4 grid, each 32(M) x 64(N) ----
    const int warp_m = wid >> 2;        // 0..3
    const int warp_n = wid & 3;         // 0..3
    const int lrow = lane & 15;
    const int lchunk = lane >> 4;       // 0/1: selects 16B chunk within k16

    // SW128 swizzle: swizzled = row*128 + (chunk_byte ^ ((row&7)<<4))
    uint32_t aRow[2], aXm[2], bRow[4], bXm[4];
#pragma unroll
    for (int mf = 0; mf < 2; ++mf) {
        int row = warp_m * 32 + mf * 16 + lrow;
        aRow[mf] = row * 128; aXm[mf] = (row & 7) << 4;
    }
#pragma unroll
    for (int nf2 = 0; nf2 < 4; ++nf2) {
        int row = warp_n * 64 + nf2 * 16 + lrow;
        bRow[nf2] = row * 128; bXm[nf2] = (row & 7) << 4;
    }

    int s = 0;
    uint32_t phase = 0;

    for (int t = blockIdx.x; t < NTILES; t += GRID) {
        int m_tile, n_tile;
        map_tile(t, m_tile, n_tile);

        float acc[2][8][4];
#pragma unroll
        for (int mf = 0; mf < 2; ++mf)
#pragma unroll
            for (int nf = 0; nf < 8; ++nf)
#pragma unroll
                for (int k = 0; k < 4; ++k) acc[mf][nf][k] = 0.0f;

        for (int it = 0; it < KITERS; ++it) {
            mbar_wait(full0 + 8 * s, phase);
            uint32_t stA = sbase + OFF_A + s * STAGE_A;
            uint32_t stB = sbase + OFF_B + s * STAGE_B;
#pragma unroll
            for (int j = 0; j < KC / 16; ++j) {
                uint32_t chunk = (uint32_t)(2 * j + lchunk) << 4;  // 16B chunk
                uint32_t a[2][4], b[4][4];
#pragma unroll
                for (int mf = 0; mf < 2; ++mf)
                    ldsm_x4(a[mf], stA + aRow[mf] + (chunk ^ aXm[mf]));
                // B is W[N,K] row-major: rows = n, cols = k. NON-trans
                // ldmatrix yields the mma.row.col B fragment directly.
#pragma unroll
                for (int nf2 = 0; nf2 < 4; ++nf2)
                    ldsm_x4(b[nf2], stB + bRow[nf2] + (chunk ^ bXm[nf2]));
                // Early stage release after the last j-step's shared reads
                // have been issued (mbarrier.arrive orders prior shared reads)
                if (j == KC / 16 - 1 && lane == 0) mbar_arrive(empty0 + 8 * s);
#pragma unroll
                for (int mf = 0; mf < 2; ++mf)
#pragma unroll
                    for (int nf = 0; nf < 8; ++nf) {
                        int nf2 = nf >> 1, sel = nf & 1;
                        mma16816(acc[mf][nf], a[mf], b[nf2][sel], b[nf2][sel + 2]);
                    }
            }
            if (++s == NSTAGES) { s = 0; phase ^= 1; }
        }

        // ---- epilogue: bias add + f32 stores; producer is already
        //      prefetching the next tile's stages into the ring ----
        const int nbase = n_tile * TN + warp_n * 64 + (lane & 3) * 2;
        const int m0 = m_tile * TM + warp_m * 32 + (lane >> 2);
#pragma unroll
        for (int mf = 0; mf < 2; ++mf) {
            int row = m0 + mf * 16;
#pragma unroll
            for (int nf = 0; nf < 8; ++nf) {
                int col = nbase + nf * 8;
                float2 bv = *reinterpret_cast<const float2*>(bias + col);
                float2 v0, v1;
                v0.x = acc[mf][nf][0] + bv.x;
                v0.y = acc[mf][nf][1] + bv.y;
                v1.x = acc[mf][nf][2] + bv.x;
                v1.y = acc[mf][nf][3] + bv.y;
                *reinterpret_cast<float2*>(out + (size_t)row * NDIM + col) = v0;
                *reinterpret_cast<float2*>(out + (size_t)(row + 8) * NDIM + col) = v1;
            }
        }
    }
}

// ---------------------------------------------------------------------------
// Host: tensor-map construction + launch
// ---------------------------------------------------------------------------
typedef CUresult (*EncodeTiledFn)(
    CUtensorMap*, CUtensorMapDataType, unsigned int, void*,
    const unsigned long long*, const unsigned long long*,
    const unsigned int*, const unsigned int*,
    CUtensorMapInterleave, CUtensorMapSwizzle, CUtensorMapL2promotion,
    CUtensorMapFloatOOBfill);

static void build_map_f16_2d(EncodeTiledFn enc, CUtensorMap* tm, void* gptr,
                             unsigned long long d0, unsigned long long d1,
                             unsigned int b0, unsigned int b1) {
    unsigned long long dims[2] = {d0, d1};
    unsigned long long strides[1] = {d0 * 2ull};
    unsigned int box[2] = {b0, b1};
    unsigned int es[2] = {1, 1};
    enc(tm, CU_TENSOR_MAP_DATA_TYPE_FLOAT16, 2, gptr, dims, strides, box, es,
        CU_TENSOR_MAP_INTERLEAVE_NONE, CU_TENSOR_MAP_SWIZZLE_128B,
        CU_TENSOR_MAP_L2_PROMOTION_L2_128B, CU_TENSOR_MAP_FLOAT_OOB_FILL_NONE);
}

extern "C" void kernel_launch(void* const* d_in, const int* in_sizes, int n_in,
                              void* d_out, int out_size) {
    // Identify inputs by element count (robust to ordering).
    const float* X = nullptr;
    const float* W = nullptr;
    const float* Bv = nullptr;
    for (int i = 0; i < n_in; ++i) {
        if (in_sizes[i] == MDIM * KDIM) X = (const float*)d_in[i];
        else if (in_sizes[i] == NDIM * KDIM) W = (const float*)d_in[i];
        else if (in_sizes[i] == NDIM) Bv = (const float*)d_in[i];
    }

    void* pX = nullptr;
    void* pW = nullptr;
    cudaGetSymbolAddress(&pX, g_X);
    cudaGetSymbolAddress(&pW, g_W);

    // f32 -> f16 conversions (quant-dequant is an exact algebraic no-op),
    // both arrays in a single launch.
    {
        int nX4 = MDIM * KDIM / 4;
        int nW4 = NDIM * KDIM / 4;
        int total = nX4 + nW4;
        int blocks = (total + 1023) / 1024;
        fp8lin_convert2_kernel<<<blocks, 256>>>((const float4*)X, (uint2*)pX, nX4,
                                                (const float4*)W, (uint2*)pW, nW4);
    }

    // TMA descriptors (host-side, capture-time; addresses stable across replays)
    void* encPtr = nullptr;
    cudaDriverEntryPointQueryResult qres;
    cudaGetDriverEntryPoint("cuTensorMapEncodeTiled", &encPtr, cudaEnableDefault, &qres);
    EncodeTiledFn enc = (EncodeTiledFn)encPtr;

    CUtensorMap tmA, tmB;
    build_map_f16_2d(enc, &tmA, pX, (unsigned long long)KDIM, (unsigned long long)MDIM,
                     KC, TM);   // box [64,128] f16 => 128B rows (SW128), 16KB
    build_map_f16_2d(enc, &tmB, pW, (unsigned long long)KDIM, (unsigned long long)NDIM,
                     KC, TN);   // box [64,256] => 32KB

    cudaFuncSetAttribute(fp8lin_gemm_kernel,
                         cudaFuncAttributeMaxDynamicSharedMemorySize, SMEM_TOTAL);
    fp8lin_gemm_kernel<<<GRID, NTHREADS, SMEM_TOTAL>>>(tmA, tmB, Bv,
                                                       (float*)d_out);
}

// round 17
// speedup vs baseline: 1.0118x; 1.0118x over previous
#include <cuda_runtime.h>
#include <cuda.h>
#include <cuda_fp16.h>
#include <cstdint>

// ---------------------------------------------------------------------------
// Problem dims (fixed for this problem instance)
// ---------------------------------------------------------------------------
static constexpr int MDIM = 8192;    // 4*2048 rows of X
static constexpr int NDIM = 16384;   // output features
static constexpr int KDIM = 4096;    // inner dim

// GEMM tiling (base-sm_103 path: TMA + ldmatrix + mma.sync.m16n8k16)
static constexpr int TM = 128;                // CTA M tile
static constexpr int TN = 256;                // CTA N tile
static constexpr int KC = 64;                 // K elems (f16) per stage = 128B rows
static constexpr int NSTAGES = 4;
static constexpr int KITERS = KDIM / KC;      // 64
static constexpr int TILES_M = MDIM / TM;     // 64
static constexpr int TILES_N = NDIM / TN;     // 64
static constexpr int NTILES = TILES_M * TILES_N;  // 4096
static constexpr int GROUP_M = 32;            // R14 mapping (best known)

static constexpr int STAGE_A = TM * KC * 2;   // 16384 B
static constexpr int STAGE_B = TN * KC * 2;   // 32768 B
static constexpr uint32_t STAGE_BYTES = STAGE_A + STAGE_B;  // 49152

// Dynamic SMEM layout
static constexpr int OFF_FULL  = 0;
static constexpr int OFF_EMPTY = OFF_FULL + NSTAGES * 8;
static constexpr int OFF_A     = 1024;
static constexpr int OFF_B     = OFF_A + NSTAGES * STAGE_A;   // 66560
static constexpr int SMEM_TOTAL = OFF_B + NSTAGES * STAGE_B;  // 197632

static constexpr int NTHREADS = 544;  // 16 compute warps + 1 TMA warp
static constexpr int GRID = 152;      // persistent: one CTA per GB300 SM

// fp16 scratch (static device arrays: the sanctioned scratch mechanism)
__device__ __half g_X[(size_t)MDIM * KDIM];   // 64 MB
__device__ __half g_W[(size_t)NDIM * KDIM];   // 128 MB

// ---------------------------------------------------------------------------
// PTX helpers (base sm_103-safe: no tcgen05 anywhere)
// ---------------------------------------------------------------------------
__device__ __forceinline__ uint32_t smem_u32(const void* p) {
    uint32_t a;
    asm("{ .reg .u64 t; cvta.to.shared.u64 t, %1; cvt.u32.u64 %0, t; }"
        : "=r"(a) : "l"(p));
    return a;
}
__device__ __forceinline__ void mbar_init(uint32_t addr, uint32_t count) {
    asm volatile("mbarrier.init.shared.b64 [%0], %1;" :: "r"(addr), "r"(count) : "memory");
}
__device__ __forceinline__ void mbar_expect_tx(uint32_t addr, uint32_t bytes) {
    asm volatile("mbarrier.arrive.expect_tx.shared.b64 _, [%0], %1;"
                 :: "r"(addr), "r"(bytes) : "memory");
}
__device__ __forceinline__ void mbar_arrive(uint32_t addr) {
    asm volatile("mbarrier.arrive.shared.b64 _, [%0];" :: "r"(addr) : "memory");
}
__device__ __forceinline__ void mbar_wait(uint32_t addr, uint32_t phase) {
    asm volatile(
        "{\n\t"
        ".reg .pred P1;\n\t"
        "LAB_WAIT_%=:\n\t"
        "mbarrier.try_wait.parity.acquire.cta.shared::cta.b64 P1, [%0], %1, 0x989680;\n\t"
        "@P1 bra.uni DONE_%=;\n\t"
        "bra.uni LAB_WAIT_%=;\n\t"
        "DONE_%=:\n\t"
        "}"
        :: "r"(addr), "r"(phase) : "memory");
}
__device__ __forceinline__ void tma_load_2d(uint32_t smem_addr, const CUtensorMap* tmap,
                                            int cx, int cy, uint32_t mbar) {
    asm volatile(
        "cp.async.bulk.tensor.2d.shared::cta.global.tile.mbarrier::complete_tx::bytes "
        "[%0], [%1, {%2, %3}], [%4];"
        :: "r"(smem_addr), "l"(tmap), "r"(cx), "r"(cy), "r"(mbar) : "memory");
}
__device__ __forceinline__ void ldsm_x4(uint32_t* r, uint32_t addr) {
    asm volatile("ldmatrix.sync.aligned.m8n8.x4.shared.b16 {%0,%1,%2,%3}, [%4];"
                 : "=r"(r[0]), "=r"(r[1]), "=r"(r[2]), "=r"(r[3]) : "r"(addr));
}
__device__ __forceinline__ void mma16816(float* c, const uint32_t* a,
                                         uint32_t b0, uint32_t b1) {
    asm volatile(
        "mma.sync.aligned.m16n8k16.row.col.f32.f16.f16.f32 "
        "{%0,%1,%2,%3}, {%4,%5,%6,%7}, {%8,%9}, {%0,%1,%2,%3};"
        : "+f"(c[0]), "+f"(c[1]), "+f"(c[2]), "+f"(c[3])
        : "r"(a[0]), "r"(a[1]), "r"(a[2]), "r"(a[3]), "r"(b0), "r"(b1));
}

// Tile index -> (m_tile, n_tile) with GROUP_M rasterization (R14 mapping)
__device__ __forceinline__ void map_tile(int t, int& m_tile, int& n_tile) {
    const int per_group = GROUP_M * TILES_N;
    int grp = t / per_group;
    int rem = t - grp * per_group;
    m_tile = grp * GROUP_M + (rem % GROUP_M);
    n_tile = rem / GROUP_M;
}

// ---------------------------------------------------------------------------
// Kernel 1: f32 -> f16 conversion for BOTH arrays in one launch
// ---------------------------------------------------------------------------
__global__ void fp8lin_convert2_kernel(const float4* __restrict__ inX,
                                       uint2* __restrict__ outX, int nX4,
                                       const float4* __restrict__ inW,
                                       uint2* __restrict__ outW, int nW4) {
    int base = blockIdx.x * (blockDim.x * 4) + threadIdx.x;
#pragma unroll
    for (int u = 0; u < 4; ++u) {
        int idx = base + u * blockDim.x;
        const float4* in;
        uint2* out;
        int rel;
        if (idx < nX4) {
            in = inX; out = outX; rel = idx;
        } else if (idx < nX4 + nW4) {
            in = inW; out = outW; rel = idx - nX4;
        } else {
            continue;
        }
        float4 v = in[rel];
        __half2 a = __floats2half2_rn(v.x, v.y);
        __half2 b = __floats2half2_rn(v.z, v.w);
        uint2 o;
        o.x = *reinterpret_cast<uint32_t*>(&a);
        o.y = *reinterpret_cast<uint32_t*>(&b);
        out[rel] = o;
    }
}

// ---------------------------------------------------------------------------
// Kernel 2: PERSISTENT pipelined HMMA GEMM  Y = Xf16 @ Wf16^T + bias
// 544 threads: warps 0-15 compute (4x4 warp grid, 32x64 tile each),
//              warp 16 = TMA producer.
// NEW: B-fragment double buffering across j-steps. R16 profile showed
// tensor pipe only 78.5% busy -- LDSM->MMA latency exposed at j-step heads.
// Prefetching j+1's B fragments (4 of 6 LDSMs) under j's MMA block closes
// most of that gap while staying within the 120-reg budget (b-next = +16).
// ---------------------------------------------------------------------------
__global__ void __launch_bounds__(NTHREADS, 1)
fp8lin_gemm_kernel(const __grid_constant__ CUtensorMap tmA,
                   const __grid_constant__ CUtensorMap tmB,
                   const float* __restrict__ bias,
                   float* __restrict__ out) {
    extern __shared__ char smem[];
    const uint32_t sbase = smem_u32(smem);
    const int tid = threadIdx.x;
    const int wid = tid >> 5;
    const int lane = tid & 31;

    const uint32_t full0 = sbase + OFF_FULL;
    const uint32_t empty0 = sbase + OFF_EMPTY;

    if (tid == 0) {
        for (int s = 0; s < NSTAGES; ++s) {
            mbar_init(full0 + 8 * s, 1);    // completed by TMA tx bytes
            mbar_init(empty0 + 8 * s, 16);  // released by 16 compute warps
        }
    }
    __syncthreads();

    if (wid == 16) {
        // ---- TMA producer: stream all tiles' K-stages through one ring ----
        if (lane == 0) {
            int s = 0;
            uint32_t phase = 1;  // fresh barrier: parity-1 wait passes immediately
            for (int t = blockIdx.x; t < NTILES; t += GRID) {
                int m_tile, n_tile;
                map_tile(t, m_tile, n_tile);
                const int my = m_tile * TM, ny = n_tile * TN;
                for (int it = 0; it < KITERS; ++it) {
                    mbar_wait(empty0 + 8 * s, phase);
                    mbar_expect_tx(full0 + 8 * s, STAGE_BYTES);
                    tma_load_2d(sbase + OFF_A + s * STAGE_A, &tmA, it * KC, my,
                                full0 + 8 * s);
                    tma_load_2d(sbase + OFF_B + s * STAGE_B, &tmB, it * KC, ny,
                                full0 + 8 * s);
                    if (++s == NSTAGES) { s = 0; phase ^= 1; }
                }
            }
        }
        return;
    }

    // ---- compute warps: 4x4 grid, each 32(M) x 64(N) ----
    const int warp_m = wid >> 2;        // 0..3
    const int warp_n = wid & 3;         // 0..3
    const int lrow = lane & 15;
    const int lchunk = lane >> 4;       // 0/1: selects 16B chunk within k16

    // SW128 swizzle: swizzled = row*128 + (chunk_byte ^ ((row&7)<<4))
    uint32_t aRow[2], aXm[2], bRow[4], bXm[4];
#pragma unroll
    for (int mf = 0; mf < 2; ++mf) {
        int row = warp_m * 32 + mf * 16 + lrow;
        aRow[mf] = row * 128; aXm[mf] = (row & 7) << 4;
    }
#pragma unroll
    for (int nf2 = 0; nf2 < 4; ++nf2) {
        int row = warp_n * 64 + nf2 * 16 + lrow;
        bRow[nf2] = row * 128; bXm[nf2] = (row & 7) << 4;
    }

    int s = 0;
    uint32_t phase = 0;

    for (int t = blockIdx.x; t < NTILES; t += GRID) {
        int m_tile, n_tile;
        map_tile(t, m_tile, n_tile);

        float acc[2][8][4];
#pragma unroll
        for (int mf = 0; mf < 2; ++mf)
#pragma unroll
            for (int nf = 0; nf < 8; ++nf)
#pragma unroll
                for (int k = 0; k < 4; ++k) acc[mf][nf][k] = 0.0f;

        for (int it = 0; it < KITERS; ++it) {
            mbar_wait(full0 + 8 * s, phase);
            uint32_t stA = sbase + OFF_A + s * STAGE_A;
            uint32_t stB = sbase + OFF_B + s * STAGE_B;

            uint32_t b[2][4][4];  // double-buffered B fragments
            // preload B for j=0
            {
                uint32_t chunk0 = (uint32_t)lchunk << 4;
#pragma unroll
                for (int nf2 = 0; nf2 < 4; ++nf2)
                    ldsm_x4(b[0][nf2], stB + bRow[nf2] + (chunk0 ^ bXm[nf2]));
            }
#pragma unroll
            for (int j = 0; j < KC / 16; ++j) {
                const int cb = j & 1, nb = cb ^ 1;
                uint32_t chunk = (uint32_t)(2 * j + lchunk) << 4;
                uint32_t a[2][4];
#pragma unroll
                for (int mf = 0; mf < 2; ++mf)
                    ldsm_x4(a[mf], stA + aRow[mf] + (chunk ^ aXm[mf]));
                if (j < KC / 16 - 1) {
                    // prefetch next j's B under this j's MMA block
                    uint32_t chunkN = (uint32_t)(2 * (j + 1) + lchunk) << 4;
#pragma unroll
                    for (int nf2 = 0; nf2 < 4; ++nf2)
                        ldsm_x4(b[nb][nf2], stB + bRow[nf2] + (chunkN ^ bXm[nf2]));
                } else if (lane == 0) {
                    // all shared reads of this stage issued -> release
                    mbar_arrive(empty0 + 8 * s);
                }
#pragma unroll
                for (int mf = 0; mf < 2; ++mf)
#pragma unroll
                    for (int nf = 0; nf < 8; ++nf) {
                        int nf2 = nf >> 1, sel = nf & 1;
                        mma16816(acc[mf][nf], a[mf], b[cb][nf2][sel], b[cb][nf2][sel + 2]);
                    }
            }
            if (++s == NSTAGES) { s = 0; phase ^= 1; }
        }

        // ---- epilogue: bias add + f32 stores; producer is already
        //      prefetching the next tile's stages into the ring ----
        const int nbase = n_tile * TN + warp_n * 64 + (lane & 3) * 2;
        const int m0 = m_tile * TM + warp_m * 32 + (lane >> 2);
#pragma unroll
        for (int mf = 0; mf < 2; ++mf) {
            int row = m0 + mf * 16;
#pragma unroll
            for (int nf = 0; nf < 8; ++nf) {
                int col = nbase + nf * 8;
                float2 bv = *reinterpret_cast<const float2*>(bias + col);
                float2 v0, v1;
                v0.x = acc[mf][nf][0] + bv.x;
                v0.y = acc[mf][nf][1] + bv.y;
                v1.x = acc[mf][nf][2] + bv.x;
                v1.y = acc[mf][nf][3] + bv.y;
                *reinterpret_cast<float2*>(out + (size_t)row * NDIM + col) = v0;
                *reinterpret_cast<float2*>(out + (size_t)(row + 8) * NDIM + col) = v1;
            }
        }
    }
}

// ---------------------------------------------------------------------------
// Host: tensor-map construction + launch
// ---------------------------------------------------------------------------
typedef CUresult (*EncodeTiledFn)(
    CUtensorMap*, CUtensorMapDataType, unsigned int, void*,
    const unsigned long long*, const unsigned long long*,
    const unsigned int*, const unsigned int*,
    CUtensorMapInterleave, CUtensorMapSwizzle, CUtensorMapL2promotion,
    CUtensorMapFloatOOBfill);

static void build_map_f16_2d(EncodeTiledFn enc, CUtensorMap* tm, void* gptr,
                             unsigned long long d0, unsigned long long d1,
                             unsigned int b0, unsigned int b1) {
    unsigned long long dims[2] = {d0, d1};
    unsigned long long strides[1] = {d0 * 2ull};
    unsigned int box[2] = {b0, b1};
    unsigned int es[2] = {1, 1};
    enc(tm, CU_TENSOR_MAP_DATA_TYPE_FLOAT16, 2, gptr, dims, strides, box, es,
        CU_TENSOR_MAP_INTERLEAVE_NONE, CU_TENSOR_MAP_SWIZZLE_128B,
        CU_TENSOR_MAP_L2_PROMOTION_L2_128B, CU_TENSOR_MAP_FLOAT_OOB_FILL_NONE);
}

extern "C" void kernel_launch(void* const* d_in, const int* in_sizes, int n_in,
                              void* d_out, int out_size) {
    // Identify inputs by element count (robust to ordering).
    const float* X = nullptr;
    const float* W = nullptr;
    const float* Bv = nullptr;
    for (int i = 0; i < n_in; ++i) {
        if (in_sizes[i] == MDIM * KDIM) X = (const float*)d_in[i];
        else if (in_sizes[i] == NDIM * KDIM) W = (const float*)d_in[i];
        else if (in_sizes[i] == NDIM) Bv = (const float*)d_in[i];
    }

    void* pX = nullptr;
    void* pW = nullptr;
    cudaGetSymbolAddress(&pX, g_X);
    cudaGetSymbolAddress(&pW, g_W);

    // f32 -> f16 conversions (quant-dequant is an exact algebraic no-op),
    // both arrays in a single launch.
    {
        int nX4 = MDIM * KDIM / 4;
        int nW4 = NDIM * KDIM / 4;
        int total = nX4 + nW4;
        int blocks = (total + 1023) / 1024;
        fp8lin_convert2_kernel<<<blocks, 256>>>((const float4*)X, (uint2*)pX, nX4,
                                                (const float4*)W, (uint2*)pW, nW4);
    }

    // TMA descriptors (host-side, capture-time; addresses stable across replays)
    void* encPtr = nullptr;
    cudaDriverEntryPointQueryResult qres;
    cudaGetDriverEntryPoint("cuTensorMapEncodeTiled", &encPtr, cudaEnableDefault, &qres);
    EncodeTiledFn enc = (EncodeTiledFn)encPtr;

    CUtensorMap tmA, tmB;
    build_map_f16_2d(enc, &tmA, pX, (unsigned long long)KDIM, (unsigned long long)MDIM,
                     KC, TM);   // box [64,128] f16 => 128B rows (SW128), 16KB
    build_map_f16_2d(enc, &tmB, pW, (unsigned long long)KDIM, (unsigned long long)NDIM,
                     KC, TN);   // box [64,256] => 32KB

    cudaFuncSetAttribute(fp8lin_gemm_kernel,
                         cudaFuncAttributeMaxDynamicSharedMemorySize, SMEM_TOTAL);
    fp8lin_gemm_kernel<<<GRID, NTHREADS, SMEM_TOTAL>>>(tmA, tmB, Bv,
                                                       (float*)d_out);
}